// round 2
// baseline (speedup 1.0000x reference)
#include <cuda_runtime.h>
#include <cstdint>

#define PI_F 3.14159265358979323846f

constexpr int NROWS   = 8192;
constexpr int DD      = 64;
constexpr int BAS     = 2048;
constexpr int ROWS    = 32;    // x-rows per CTA
constexpr int BK      = 32;    // basis tile
constexpr int THREADS = 128;

// scratch (allocation-free per harness rules)
__device__ float g_St[DD * BAS];   // [d][b] = eps[b][d] / (pi * lam[d])
__device__ float g_WS[BAS * DD];   // [b][c] = -mat[b][c] * w_s[b]
__device__ float g_WC[BAS * DD];   // [b][c] =  mat[b][c] * w_c[b]

typedef unsigned long long u64;

__device__ __forceinline__ u64 pack2(float lo, float hi) {
  u64 r; asm("mov.b64 %0, {%1, %2};" : "=l"(r) : "f"(lo), "f"(hi)); return r;
}
__device__ __forceinline__ void unpack2(u64 a, float& lo, float& hi) {
  asm("mov.b64 {%0, %1}, %2;" : "=f"(lo), "=f"(hi) : "l"(a));
}
__device__ __forceinline__ u64 fma2(u64 a, u64 b, u64 c) {
  u64 d; asm("fma.rn.f32x2 %0, %1, %2, %3;" : "=l"(d) : "l"(a), "l"(b), "l"(c)); return d;
}

__global__ void precompute_kernel(const float* __restrict__ eps,
                                  const float* __restrict__ lam,
                                  const float* __restrict__ eta,
                                  const float* __restrict__ w) {
  int idx = blockIdx.x * blockDim.x + threadIdx.x;
  if (idx >= BAS * DD) return;
  int b = idx >> 6;
  int d = idx & 63;
  float lam_d = lam[d];
  float e     = eps[idx];
  // sim = 2*pi*(x . eps/(2*pi*lam)) = pi * (x . eps/(pi*lam))
  g_St[d * BAS + b] = e / (PI_F * lam_d);
  float m;
  if (d < 32) {
    m = eps[b * DD + d + 32] / lam[d + 32];
  } else {
    float et = eta[0];
    m = -eps[b * DD + d - 32] / lam[d - 32] - (et * et) * (e / lam_d);
  }
  g_WS[idx] = -m * w[b];         // sign of -sin folded in
  g_WC[idx] =  m * w[BAS + b];
}

__global__ __launch_bounds__(THREADS, 4)
void ssgp_main_kernel(const float* __restrict__ x, float* __restrict__ out) {
  __shared__ float Xt[DD][36];          // [d][r], stride 144B (16B aligned)
  __shared__ float St[DD][BK];          // [d][b], rows 128B dense
  __shared__ float Pt[2 * BK][36];      // [k][r]; k<32: sin, k>=32: cos
  __shared__ float Wsm[2 * BK][DD];     // [k][c]; k<32: -w_s*mat, k>=32: w_c*mat

  const int tid = threadIdx.x;
  const int r0  = blockIdx.x * ROWS;
  const int ty  = tid >> 4;   // 0..7  -> rows 4ty..4ty+3
  const int tx  = tid & 15;   // 0..15 -> GEMM1 basis {2tx,2tx+1}; GEMM2 cols 4tx..4tx+3

  // ---- Load X tile (32 rows x 64 dims), transpose into Xt[d][r] ----
  #pragma unroll
  for (int i = 0; i < 4; i++) {
    int j  = tid + i * THREADS;       // 0..511 float4s
    int r  = j >> 4;                  // 0..31
    int d4 = (j & 15) * 4;
    float4 v = *reinterpret_cast<const float4*>(&x[(size_t)(r0 + r) * DD + d4]);
    Xt[d4 + 0][r] = v.x;
    Xt[d4 + 1][r] = v.y;
    Xt[d4 + 2][r] = v.z;
    Xt[d4 + 3][r] = v.w;
  }

  // persistent f accumulators: 4 rows x 4 cols as packed f32x2
  u64 f[4][2] = {};

  for (int bt = 0; bt < BAS / BK; bt++) {
    const int b0 = bt * BK;

    // ---- stage St tile: 64 d-rows x 32 basis ----
    #pragma unroll
    for (int i = 0; i < 4; i++) {
      int j   = tid + i * THREADS;    // 0..511
      int d   = j >> 3;               // 0..63
      int bb4 = (j & 7) * 4;
      *reinterpret_cast<float4*>(&St[d][bb4]) =
          *reinterpret_cast<const float4*>(&g_St[(size_t)d * BAS + b0 + bb4]);
    }
    // ---- stage W tile: 64 k-rows x 64 cols ----
    #pragma unroll
    for (int i = 0; i < 8; i++) {
      int j  = tid + i * THREADS;     // 0..1023
      int kk = j >> 4;                // 0..63
      int c4 = (j & 15) * 4;
      const float* src = (kk < BK) ? &g_WS[(size_t)(b0 + kk) * DD + c4]
                                   : &g_WC[(size_t)(b0 + kk - BK) * DD + c4];
      *reinterpret_cast<float4*>(&Wsm[kk][c4]) = *reinterpret_cast<const float4*>(src);
    }
    __syncthreads();

    // ---- GEMM1: a[r][b] = sum_d Xt[d][r] * St[d][b]  (4 rows x 2 basis / thread) ----
    u64 a[4] = {};
    #pragma unroll 16
    for (int k = 0; k < DD; k++) {
      float4 xv = *reinterpret_cast<const float4*>(&Xt[k][4 * ty]);
      u64    sv = *reinterpret_cast<const u64*>(&St[k][2 * tx]);
      a[0] = fma2(pack2(xv.x, xv.x), sv, a[0]);
      a[1] = fma2(pack2(xv.y, xv.y), sv, a[1]);
      a[2] = fma2(pack2(xv.z, xv.z), sv, a[2]);
      a[3] = fma2(pack2(xv.w, xv.w), sv, a[3]);
    }

    // ---- sincos(pi * a) with exact mod-2 reduction; write transposed into Pt ----
    #pragma unroll
    for (int p = 0; p < 2; p++) {
      float s[4], c[4];
      #pragma unroll
      for (int r = 0; r < 4; r++) {
        float lo, hi; unpack2(a[r], lo, hi);
        float v  = p ? hi : lo;
        float ar = fmaf(-2.0f, rintf(v * 0.5f), v);
        __sincosf(ar * PI_F, &s[r], &c[r]);
      }
      *reinterpret_cast<float4*>(&Pt[2 * tx + p][4 * ty])      = make_float4(s[0], s[1], s[2], s[3]);
      *reinterpret_cast<float4*>(&Pt[BK + 2 * tx + p][4 * ty]) = make_float4(c[0], c[1], c[2], c[3]);
    }
    __syncthreads();

    // ---- GEMM2: f[r][c] += sum_k Pt[k][r] * Wsm[k][c]  (4 rows x 4 cols / thread) ----
    #pragma unroll 8
    for (int k = 0; k < 2 * BK; k++) {
      float4     pv = *reinterpret_cast<const float4*>(&Pt[k][4 * ty]);
      ulonglong2 wv = *reinterpret_cast<const ulonglong2*>(&Wsm[k][4 * tx]);
      u64 p0 = pack2(pv.x, pv.x);
      u64 p1 = pack2(pv.y, pv.y);
      u64 p2 = pack2(pv.z, pv.z);
      u64 p3 = pack2(pv.w, pv.w);
      f[0][0] = fma2(p0, wv.x, f[0][0]);
      f[0][1] = fma2(p0, wv.y, f[0][1]);
      f[1][0] = fma2(p1, wv.x, f[1][0]);
      f[1][1] = fma2(p1, wv.y, f[1][1]);
      f[2][0] = fma2(p2, wv.x, f[2][0]);
      f[2][1] = fma2(p2, wv.y, f[2][1]);
      f[3][0] = fma2(p3, wv.x, f[3][0]);
      f[3][1] = fma2(p3, wv.y, f[3][1]);
    }
    __syncthreads();
  }

  // ---- epilogue: write f (coalesced float4 per row) ----
  #pragma unroll
  for (int r = 0; r < 4; r++) {
    float o0, o1, o2, o3;
    unpack2(f[r][0], o0, o1);
    unpack2(f[r][1], o2, o3);
    *reinterpret_cast<float4*>(&out[(size_t)(r0 + 4 * ty + r) * DD + 4 * tx]) =
        make_float4(o0, o1, o2, o3);
  }
}

extern "C" void kernel_launch(void* const* d_in, const int* in_sizes, int n_in,
                              void* d_out, int out_size) {
  // inputs (metadata order): t, x, epsilon, lam, eta, w
  const float* x_in = (const float*)d_in[1];
  const float* eps  = (const float*)d_in[2];
  const float* lam  = (const float*)d_in[3];
  const float* eta  = (const float*)d_in[4];
  const float* w    = (const float*)d_in[5];
  float* out = (float*)d_out;

  precompute_kernel<<<(BAS * DD + 255) / 256, 256>>>(eps, lam, eta, w);
  ssgp_main_kernel<<<NROWS / ROWS, THREADS>>>(x_in, out);
}

// round 3
// speedup vs baseline: 2.2123x; 2.2123x over previous
#include <cuda_runtime.h>
#include <cstdint>

#define PI_F 3.14159265358979323846f

constexpr int NROWS    = 8192;
constexpr int DD       = 64;
constexpr int BAS      = 2048;
constexpr int ROWS_CTA = 256;   // 8 warps x 32-row bands
constexpr int BK       = 64;    // basis per tile
constexpr int SPLITS   = 8;     // basis split across CTAs
constexpr int BAS_CTA  = BAS / SPLITS;   // 256
constexpr int TILES    = BAS_CTA / BK;   // 4
constexpr int THREADS  = 256;

// smem layout (floats)
constexpr int OFF_XT = 0;                  // [64][256]
constexpr int OFF_ST = 16384;              // [64][64]  (granule-permuted)
constexpr int OFF_W  = 20480;              // [128][64] (granule-permuted rows, see mapping)
constexpr int OFF_PT = 28672;              // [64][260]
constexpr int SMEM_FLOATS = OFF_PT + 64 * 260;          // 45312
constexpr int SMEM_BYTES  = SMEM_FLOATS * 4;            // 181248

// scratch (static device arrays: allocation-free)
__device__ float g_St[DD * BAS];              // [d][b] = eps[b][d] / (pi*lam[d])
__device__ float g_WS[BAS * DD];              // [b][c] = -mat*w_s
__device__ float g_WC[BAS * DD];              // [b][c] =  mat*w_c
__device__ float g_part[SPLITS * NROWS * DD]; // 16MB partials

typedef unsigned long long u64;

__device__ __forceinline__ u64 pack2(float lo, float hi) {
  u64 r; asm("mov.b64 %0, {%1, %2};" : "=l"(r) : "f"(lo), "f"(hi)); return r;
}
__device__ __forceinline__ void unpack2(u64 a, float& lo, float& hi) {
  asm("mov.b64 {%0, %1}, %2;" : "=f"(lo), "=f"(hi) : "l"(a));
}
__device__ __forceinline__ u64 fma2(u64 a, u64 b, u64 c) {
  u64 d; asm("fma.rn.f32x2 %0, %1, %2, %3;" : "=l"(d) : "l"(a), "l"(b), "l"(c)); return d;
}

__global__ void precompute_kernel(const float* __restrict__ eps,
                                  const float* __restrict__ lam,
                                  const float* __restrict__ eta,
                                  const float* __restrict__ w) {
  int idx = blockIdx.x * blockDim.x + threadIdx.x;
  if (idx >= BAS * DD) return;
  int b = idx >> 6;
  int d = idx & 63;
  float lam_d = lam[d];
  float e     = eps[idx];
  g_St[d * BAS + b] = e / (PI_F * lam_d);   // angle = pi * (x . col)
  float m;
  if (d < 32) {
    m = eps[b * DD + d + 32] / lam[d + 32];
  } else {
    float et = eta[0];
    m = -eps[b * DD + d - 32] / lam[d - 32] - (et * et) * (e / lam_d);
  }
  g_WS[idx] = -m * w[b];
  g_WC[idx] =  m * w[BAS + b];
}

__global__ __launch_bounds__(THREADS, 1)
void ssgp_main_kernel(const float* __restrict__ x) {
  extern __shared__ float smem[];
  float* Xt  = smem + OFF_XT;   // [d][r]   r stride 256
  float* St  = smem + OFF_ST;   // [k][16 granules]  granule g -> cols (g&7)*8+(g>>3)*4 ..+3
  float* Wsm = smem + OFF_W;    // [128][16 granules] same col perm
  float* Pt  = smem + OFF_PT;   // [krow][260]

  const int tid  = threadIdx.x;
  const int w    = tid >> 5;        // warp 0..7 -> row band 32w
  const int lane = tid & 31;
  const int rowg = lane >> 3;       // 0..3 -> rows 8*rowg
  const int cg   = lane & 7;        // 0..7 -> 8 basis / 8 cols
  const int rb   = blockIdx.x >> 3;
  const int sp   = blockIdx.x & 7;
  const int r0   = rb * ROWS_CTA;
  const int rloc = 32 * w + 8 * rowg;  // this thread's first row (local)

  // ---- stage X tile: 256 rows x 64 d, transposed ----
  #pragma unroll
  for (int i = 0; i < 16; i++) {
    int j  = tid + i * THREADS;     // 0..4095 float4s
    int r  = j >> 4;                // 0..255
    int d4 = (j & 15) * 4;
    float4 v = *reinterpret_cast<const float4*>(&x[(size_t)(r0 + r) * DD + d4]);
    Xt[(d4 + 0) * 256 + r] = v.x;
    Xt[(d4 + 1) * 256 + r] = v.y;
    Xt[(d4 + 2) * 256 + r] = v.z;
    Xt[(d4 + 3) * 256 + r] = v.w;
  }

  u64 f[8][4] = {};   // f[r][c2]: rows rloc..+7, cols 8cg..8cg+7

  for (int t = 0; t < TILES; t++) {
    const int b0 = sp * BAS_CTA + t * BK;
    __syncthreads();   // prior tile's readers done before restaging

    // ---- stage St: 64 k x 16 granules ----
    #pragma unroll
    for (int i = 0; i < 4; i++) {
      int g  = tid + i * THREADS;   // granule id 0..1023
      int k  = g >> 4;
      int gr = g & 15;
      int cb = (gr & 7) * 8 + (gr >> 3) * 4;
      *reinterpret_cast<float4*>(&St[k * 64 + gr * 4]) =
          *reinterpret_cast<const float4*>(&g_St[(size_t)k * BAS + b0 + cb]);
    }
    // ---- stage Wsm: 128 rows x 16 granules ----
    // row = 64h + isc*32 + jj*8 + c  holds (isc? WC:WS) for basis bb = 8c + 4h + jj
    #pragma unroll
    for (int i = 0; i < 8; i++) {
      int g   = tid + i * THREADS;  // 0..2047
      int row = g >> 4;
      int gr  = g & 15;
      int h   = row >> 6;
      int rem = row & 63;
      int isc = rem >> 5;
      int jj  = (rem >> 3) & 3;
      int c   = rem & 7;
      int bb  = 8 * c + 4 * h + jj;
      int cb  = (gr & 7) * 8 + (gr >> 3) * 4;
      const float* src = (isc ? g_WC : g_WS) + (size_t)(b0 + bb) * DD + cb;
      *reinterpret_cast<float4*>(&Wsm[row * 64 + gr * 4]) =
          *reinterpret_cast<const float4*>(src);
    }
    __syncthreads();

    // ---- GEMM1: a[r][jp], basis j = 8*cg + (2*jp + lo/hi) ----
    u64 a[8][4] = {};
    #pragma unroll 8
    for (int k = 0; k < DD; k++) {
      float4 x0 = *reinterpret_cast<const float4*>(&Xt[k * 256 + rloc]);
      float4 x1 = *reinterpret_cast<const float4*>(&Xt[k * 256 + rloc + 4]);
      ulonglong2 sl = reinterpret_cast<const ulonglong2*>(&St[k * 64])[cg];
      ulonglong2 sh = reinterpret_cast<const ulonglong2*>(&St[k * 64])[cg + 8];
      float xr[8] = {x0.x, x0.y, x0.z, x0.w, x1.x, x1.y, x1.z, x1.w};
      #pragma unroll
      for (int r = 0; r < 8; r++) {
        u64 xx = pack2(xr[r], xr[r]);
        a[r][0] = fma2(xx, sl.x, a[r][0]);
        a[r][1] = fma2(xx, sl.y, a[r][1]);
        a[r][2] = fma2(xx, sh.x, a[r][2]);
        a[r][3] = fma2(xx, sh.y, a[r][3]);
      }
    }

    // ---- two half-passes: sincos + Pt store, then GEMM2 over 64 k-rows ----
    #pragma unroll
    for (int h = 0; h < 2; h++) {
      #pragma unroll
      for (int jdx = 0; jdx < 4; jdx++) {
        int jp  = 2 * h + (jdx >> 1);
        int sel = jdx & 1;
        float sv[8], cv[8];
        #pragma unroll
        for (int r = 0; r < 8; r++) {
          float lo, hi; unpack2(a[r][jp], lo, hi);
          float v  = sel ? hi : lo;
          float ar = fmaf(-2.0f, rintf(v * 0.5f), v);
          __sincosf(ar * PI_F, &sv[r], &cv[r]);
        }
        int row  = jdx * 8 + cg;
        int base = row * 260 + rloc;
        *reinterpret_cast<float4*>(&Pt[base])     = make_float4(sv[0], sv[1], sv[2], sv[3]);
        *reinterpret_cast<float4*>(&Pt[base + 4]) = make_float4(sv[4], sv[5], sv[6], sv[7]);
        *reinterpret_cast<float4*>(&Pt[base + 32 * 260])     = make_float4(cv[0], cv[1], cv[2], cv[3]);
        *reinterpret_cast<float4*>(&Pt[base + 32 * 260 + 4]) = make_float4(cv[4], cv[5], cv[6], cv[7]);
      }
      __syncwarp();

      #pragma unroll 4
      for (int kk = 0; kk < 64; kk++) {
        float4 p0 = *reinterpret_cast<const float4*>(&Pt[kk * 260 + rloc]);
        float4 p1 = *reinterpret_cast<const float4*>(&Pt[kk * 260 + rloc + 4]);
        ulonglong2 wl = reinterpret_cast<const ulonglong2*>(&Wsm[(64 * h + kk) * 64])[cg];
        ulonglong2 wh = reinterpret_cast<const ulonglong2*>(&Wsm[(64 * h + kk) * 64])[cg + 8];
        float pr[8] = {p0.x, p0.y, p0.z, p0.w, p1.x, p1.y, p1.z, p1.w};
        #pragma unroll
        for (int r = 0; r < 8; r++) {
          u64 pp = pack2(pr[r], pr[r]);
          f[r][0] = fma2(pp, wl.x, f[r][0]);
          f[r][1] = fma2(pp, wl.y, f[r][1]);
          f[r][2] = fma2(pp, wh.x, f[r][2]);
          f[r][3] = fma2(pp, wh.y, f[r][3]);
        }
      }
      __syncwarp();
    }
  }

  // ---- epilogue: partials ----
  float* po = g_part + (size_t)sp * NROWS * DD;
  #pragma unroll
  for (int r = 0; r < 8; r++) {
    float o[8];
    unpack2(f[r][0], o[0], o[1]);
    unpack2(f[r][1], o[2], o[3]);
    unpack2(f[r][2], o[4], o[5]);
    unpack2(f[r][3], o[6], o[7]);
    size_t base = (size_t)(r0 + rloc + r) * DD + 8 * cg;
    *reinterpret_cast<float4*>(&po[base])     = make_float4(o[0], o[1], o[2], o[3]);
    *reinterpret_cast<float4*>(&po[base + 4]) = make_float4(o[4], o[5], o[6], o[7]);
  }
}

__global__ void reduce_kernel(float* __restrict__ out) {
  int i = blockIdx.x * blockDim.x + threadIdx.x;   // float4 index
  constexpr int N4 = NROWS * DD / 4;               // 131072
  if (i >= N4) return;
  const float4* p = reinterpret_cast<const float4*>(g_part);
  float4 acc = p[i];
  #pragma unroll
  for (int s = 1; s < SPLITS; s++) {
    float4 v = p[(size_t)s * N4 + i];
    acc.x += v.x; acc.y += v.y; acc.z += v.z; acc.w += v.w;
  }
  reinterpret_cast<float4*>(out)[i] = acc;
}

extern "C" void kernel_launch(void* const* d_in, const int* in_sizes, int n_in,
                              void* d_out, int out_size) {
  // inputs (metadata order): t, x, epsilon, lam, eta, w
  const float* x_in = (const float*)d_in[1];
  const float* eps  = (const float*)d_in[2];
  const float* lam  = (const float*)d_in[3];
  const float* eta  = (const float*)d_in[4];
  const float* w    = (const float*)d_in[5];
  float* out = (float*)d_out;

  cudaFuncSetAttribute(ssgp_main_kernel,
                       cudaFuncAttributeMaxDynamicSharedMemorySize, SMEM_BYTES);

  precompute_kernel<<<(BAS * DD + 255) / 256, 256>>>(eps, lam, eta, w);
  ssgp_main_kernel<<<(NROWS / ROWS_CTA) * SPLITS, THREADS, SMEM_BYTES>>>(x_in);
  reduce_kernel<<<(NROWS * DD / 4 + 255) / 256, 256>>>(out);
}

// round 5
// speedup vs baseline: 4.5811x; 2.0707x over previous
#include <cuda_runtime.h>
#include <cuda_bf16.h>
#include <cstdint>

#define PI_F 3.14159265358979323846f

constexpr int NROWS = 8192, DD = 64, BAS = 2048;
constexpr int MROWS   = 128;                 // rows per CTA (8 warps x 16)
constexpr int NB      = 64;                  // basis per iteration
constexpr int SPLITS  = 2;
constexpr int ITERS   = BAS / SPLITS / NB;   // 16
constexpr int THREADS = 256;

// smem byte offsets
constexpr int OFF_SHI = 0;        // 64 x 72 bf16 = 9216
constexpr int OFF_SLO = 9216;     // 64 x 72 bf16
constexpr int OFF_WHI = 18432;    // 64 x 136 bf16 = 17408  (k: 0..63 sin, 64..127 cos)
constexpr int OFF_WLO = 35840;    // 64 x 136 bf16
constexpr int OFF_XS  = OFF_WHI;  // overlay scratch: 128 x 68 f32 = 34816 (dead after prolog)
constexpr int SMEM_BYTES = 53248;

__device__ __nv_bfloat16 g_Shi[BAS * DD], g_Slo[BAS * DD];   // [b][d]
__device__ __nv_bfloat16 g_Wsh[DD * BAS], g_Wsl[DD * BAS];   // [c][b]  sin coeff (-mat*w_s)
__device__ __nv_bfloat16 g_Wch[DD * BAS], g_Wcl[DD * BAS];   // [c][b]  cos coeff ( mat*w_c)
__device__ float g_part[SPLITS * NROWS * DD];

__device__ __forceinline__ uint32_t cvt2(float lo, float hi) {
  uint32_t r;
  asm("cvt.rn.satfinite.bf16x2.f32 %0, %1, %2;" : "=r"(r) : "f"(hi), "f"(lo));
  return r;
}
// split (v0,v1) into bf16x2 hi + bf16x2 lo residual
__device__ __forceinline__ void split2(float v0, float v1, uint32_t& hi, uint32_t& lo) {
  hi = cvt2(v0, v1);
  float r0 = v0 - __uint_as_float(hi << 16);
  float r1 = v1 - __uint_as_float(hi & 0xFFFF0000u);
  lo = cvt2(r0, r1);
}
__device__ __forceinline__ void mma16816(float* d, const uint32_t* a, uint32_t b0, uint32_t b1) {
  asm volatile(
      "mma.sync.aligned.m16n8k16.row.col.f32.bf16.bf16.f32 "
      "{%0,%1,%2,%3}, {%4,%5,%6,%7}, {%8,%9}, {%0,%1,%2,%3};"
      : "+f"(d[0]), "+f"(d[1]), "+f"(d[2]), "+f"(d[3])
      : "r"(a[0]), "r"(a[1]), "r"(a[2]), "r"(a[3]), "r"(b0), "r"(b1));
}

__global__ void precompute_kernel(const float* __restrict__ eps,
                                  const float* __restrict__ lam,
                                  const float* __restrict__ eta,
                                  const float* __restrict__ w) {
  int idx = blockIdx.x * blockDim.x + threadIdx.x;
  if (idx >= BAS * DD) return;
  int b = idx >> 6, d = idx & 63;
  float e = eps[idx], la = lam[d];
  float sv = e / (PI_F * la);                 // angle = pi * (x . col)
  __nv_bfloat16 h = __float2bfloat16(sv);
  g_Shi[idx] = h;
  g_Slo[idx] = __float2bfloat16(sv - __bfloat162float(h));
  float m;
  if (d < 32) {
    m = eps[b * 64 + d + 32] / lam[d + 32];
  } else {
    float et = eta[0];
    m = -eps[b * 64 + d - 32] / lam[d - 32] - et * et * (e / la);
  }
  float ws = -m * w[b];          // -sin sign folded in
  float wc =  m * w[BAS + b];
  h = __float2bfloat16(ws);
  g_Wsh[d * BAS + b] = h;
  g_Wsl[d * BAS + b] = __float2bfloat16(ws - __bfloat162float(h));
  h = __float2bfloat16(wc);
  g_Wch[d * BAS + b] = h;
  g_Wcl[d * BAS + b] = __float2bfloat16(wc - __bfloat162float(h));
}

__global__ __launch_bounds__(THREADS, 1)
void ssgp_mma_kernel(const float* __restrict__ x) {
  extern __shared__ char sm[];
  const int tid  = threadIdx.x;
  const int wid  = tid >> 5;
  const int lane = tid & 31;
  const int gr   = lane >> 2;         // group row 0..7
  const int kl   = (lane & 3) * 2;    // k-pair base 0,2,4,6
  const int rb   = blockIdx.x >> 1;
  const int sp   = blockIdx.x & 1;
  const int r0   = rb * MROWS;

  // ---- prolog: stage X fp32 into scratch (coalesced), extract persistent A-frags ----
  {
    float* Xs = reinterpret_cast<float*>(sm + OFF_XS);   // [128][68]
    #pragma unroll
    for (int i = 0; i < 8; i++) {
      int id  = tid + i * THREADS;     // 0..2047 float4s
      int row = id >> 4;
      int c4  = (id & 15) * 4;
      *reinterpret_cast<float4*>(&Xs[row * 68 + c4]) =
          *reinterpret_cast<const float4*>(&x[(size_t)(r0 + row) * DD + c4]);
    }
  }
  __syncthreads();
  uint32_t Xhi[4][4], Xlo[4][4];
  {
    const float* Xs = reinterpret_cast<const float*>(sm + OFF_XS);
    #pragma unroll
    for (int kt = 0; kt < 4; kt++)
      #pragma unroll
      for (int q = 0; q < 4; q++) {
        int rr = wid * 16 + gr + (q & 1) * 8;
        int kk = kt * 16 + kl + (q >> 1) * 8;
        float2 v = *reinterpret_cast<const float2*>(&Xs[rr * 68 + kk]);
        split2(v.x, v.y, Xhi[kt][q], Xlo[kt][q]);
      }
  }
  __syncthreads();

  float f[8][4] = {};   // persistent output accum: 8 n-tiles x 4 regs

  #pragma unroll 1
  for (int it = 0; it < ITERS; it++) {
    const int b0 = sp * (BAS / SPLITS) + it * NB;

    // ---- stage S tiles (hi/lo): 64 x 64 bf16 each, row pad 72 ----
    #pragma unroll
    for (int i = 0; i < 4; i++) {
      int id   = tid + i * THREADS;    // 0..1023 granules (16B)
      int tile = id >> 9;
      int rem  = id & 511;
      int row  = rem >> 3;
      int c8   = rem & 7;
      const __nv_bfloat16* src = (tile ? g_Slo : g_Shi) + (size_t)(b0 + row) * DD + c8 * 8;
      char* dst = sm + (tile ? OFF_SLO : OFF_SHI) + (row * 72 + c8 * 8) * 2;
      *reinterpret_cast<uint4*>(dst) = *reinterpret_cast<const uint4*>(src);
    }
    // ---- stage W tiles (hi/lo): 64 x 128 bf16 each, row pad 136; k 0..63 sin, 64..127 cos ----
    #pragma unroll
    for (int i = 0; i < 8; i++) {
      int id   = tid + i * THREADS;    // 0..2047 granules
      int tile = id >> 10;
      int rem  = id & 1023;
      int row  = rem >> 4;
      int part = (rem >> 3) & 1;
      int c8   = rem & 7;
      const __nv_bfloat16* src =
          (tile ? (part ? g_Wcl : g_Wsl) : (part ? g_Wch : g_Wsh)) + (size_t)row * BAS + b0 + c8 * 8;
      char* dst = sm + (tile ? OFF_WLO : OFF_WHI) + (row * 136 + part * 64 + c8 * 8) * 2;
      *reinterpret_cast<uint4*>(dst) = *reinterpret_cast<const uint4*>(src);
    }
    __syncthreads();

    // ---- 4 basis-pairs: GEMM1 (reg angles) -> sincos/split -> GEMM2 accumulate ----
    #pragma unroll
    for (int p = 0; p < 4; p++) {
      // GEMM1: D[j] = X(16x64) . S^T for n-tiles 2p, 2p+1 (3 split passes, B reused)
      float D[2][4] = {};
      #pragma unroll
      for (int kt = 0; kt < 4; kt++) {
        #pragma unroll
        for (int j = 0; j < 2; j++) {
          int e = ((2 * p + j) * 8 + gr) * 72 + kt * 16 + kl;
          const char* sh = sm + OFF_SHI + e * 2;
          const char* sl = sm + OFF_SLO + e * 2;
          uint32_t bh0 = *reinterpret_cast<const uint32_t*>(sh);
          uint32_t bh1 = *reinterpret_cast<const uint32_t*>(sh + 16);
          uint32_t bl0 = *reinterpret_cast<const uint32_t*>(sl);
          uint32_t bl1 = *reinterpret_cast<const uint32_t*>(sl + 16);
          mma16816(D[j], Xhi[kt], bh0, bh1);
          mma16816(D[j], Xhi[kt], bl0, bl1);
          mma16816(D[j], Xlo[kt], bh0, bh1);
        }
      }

      // sincos + bf16 split, packed directly as GEMM2 A-frags (D-frag == A-frag layout)
      uint32_t Ash[4], Asl[4], Ach[4], Acl[4];
      #pragma unroll
      for (int j = 0; j < 2; j++)
        #pragma unroll
        for (int h = 0; h < 2; h++) {
          float v0 = D[j][2 * h], v1 = D[j][2 * h + 1];
          float a0 = fmaf(-2.0f, rintf(v0 * 0.5f), v0) * PI_F;
          float a1 = fmaf(-2.0f, rintf(v1 * 0.5f), v1) * PI_F;
          float s0, c0, s1, c1;
          __sincosf(a0, &s0, &c0);
          __sincosf(a1, &s1, &c1);
          int idx = 2 * j + h;
          split2(s0, s1, Ash[idx], Asl[idx]);
          split2(c0, c1, Ach[idx], Acl[idx]);
        }

      // GEMM2: f[nt] += P(16x16 sin | 16x16 cos) . W^T  (3 split passes)
      #pragma unroll
      for (int nt = 0; nt < 8; nt++) {
        int ebase = (nt * 8 + gr) * 136 + kl;
        {
          int e = ebase + 16 * p;                 // sin k-tile
          const char* wh = sm + OFF_WHI + e * 2;
          const char* wl = sm + OFF_WLO + e * 2;
          uint32_t h0 = *reinterpret_cast<const uint32_t*>(wh);
          uint32_t h1 = *reinterpret_cast<const uint32_t*>(wh + 16);
          uint32_t l0 = *reinterpret_cast<const uint32_t*>(wl);
          uint32_t l1 = *reinterpret_cast<const uint32_t*>(wl + 16);
          mma16816(f[nt], Ash, h0, h1);
          mma16816(f[nt], Ash, l0, l1);
          mma16816(f[nt], Asl, h0, h1);
        }
        {
          int e = ebase + 64 + 16 * p;            // cos k-tile
          const char* wh = sm + OFF_WHI + e * 2;
          const char* wl = sm + OFF_WLO + e * 2;
          uint32_t h0 = *reinterpret_cast<const uint32_t*>(wh);
          uint32_t h1 = *reinterpret_cast<const uint32_t*>(wh + 16);
          uint32_t l0 = *reinterpret_cast<const uint32_t*>(wl);
          uint32_t l1 = *reinterpret_cast<const uint32_t*>(wl + 16);
          mma16816(f[nt], Ach, h0, h1);
          mma16816(f[nt], Ach, l0, l1);
          mma16816(f[nt], Acl, h0, h1);
        }
      }
    }
    __syncthreads();   // before restaging next tile
  }

  // ---- epilogue: write partials ----
  {
    float* po = g_part + (size_t)sp * NROWS * DD;
    int row = r0 + wid * 16 + gr;
    #pragma unroll
    for (int nt = 0; nt < 8; nt++) {
      int col = nt * 8 + kl;
      *reinterpret_cast<float2*>(&po[(size_t)row * DD + col]) =
          make_float2(f[nt][0], f[nt][1]);
      *reinterpret_cast<float2*>(&po[(size_t)(row + 8) * DD + col]) =
          make_float2(f[nt][2], f[nt][3]);
    }
  }
}

__global__ void reduce_kernel(float* __restrict__ out) {
  int i = blockIdx.x * blockDim.x + threadIdx.x;
  constexpr int N4 = NROWS * DD / 4;
  if (i >= N4) return;
  const float4* p = reinterpret_cast<const float4*>(g_part);
  float4 a = p[i];
  float4 b = p[(size_t)N4 + i];
  a.x += b.x; a.y += b.y; a.z += b.z; a.w += b.w;
  reinterpret_cast<float4*>(out)[i] = a;
}

extern "C" void kernel_launch(void* const* d_in, const int* in_sizes, int n_in,
                              void* d_out, int out_size) {
  // inputs (metadata order): t, x, epsilon, lam, eta, w
  const float* x_in = (const float*)d_in[1];
  const float* eps  = (const float*)d_in[2];
  const float* lam  = (const float*)d_in[3];
  const float* eta  = (const float*)d_in[4];
  const float* w    = (const float*)d_in[5];
  float* out = (float*)d_out;

  cudaFuncSetAttribute(ssgp_mma_kernel,
                       cudaFuncAttributeMaxDynamicSharedMemorySize, SMEM_BYTES);

  precompute_kernel<<<(BAS * DD + 255) / 256, 256>>>(eps, lam, eta, w);
  ssgp_mma_kernel<<<(NROWS / MROWS) * SPLITS, THREADS, SMEM_BYTES>>>(x_in);
  reduce_kernel<<<(NROWS * DD / 4 + 255) / 256, 256>>>(out);
}

// round 6
// speedup vs baseline: 4.7766x; 1.0427x over previous
#include <cuda_runtime.h>
#include <cuda_bf16.h>
#include <cstdint>

#define PI_F 3.14159265358979323846f

constexpr int NROWS = 8192, DD = 64, BAS = 2048;
constexpr int MROWS   = 128;                 // rows per CTA (8 warps x 16)
constexpr int NB      = 64;                  // basis per iteration
constexpr int SPLITS  = 4;
constexpr int ITERS   = BAS / SPLITS / NB;   // 8
constexpr int THREADS = 256;

// smem byte offsets
constexpr int OFF_SHI = 0;        // 64 x 72 bf16 = 9216
constexpr int OFF_SLO = 9216;     // 64 x 72 bf16
constexpr int OFF_WHI = 18432;    // 64 x 136 bf16 = 17408  (k: 0..63 sin, 64..127 cos)
constexpr int OFF_WLO = 35840;    // 64 x 136 bf16
constexpr int OFF_XS  = OFF_WHI;  // overlay scratch: 128 x 68 f32 = 34816 (dead after prolog)
constexpr int SMEM_BYTES = 53248;

__device__ __nv_bfloat16 g_Shi[BAS * DD], g_Slo[BAS * DD];   // [b][d]
__device__ __nv_bfloat16 g_Wsh[DD * BAS], g_Wsl[DD * BAS];   // [c][b]  sin coeff (-mat*w_s)
__device__ __nv_bfloat16 g_Wch[DD * BAS], g_Wcl[DD * BAS];   // [c][b]  cos coeff ( mat*w_c)
__device__ float g_part[SPLITS * NROWS * DD];

__device__ __forceinline__ uint32_t cvt2(float lo, float hi) {
  uint32_t r;
  asm("cvt.rn.satfinite.bf16x2.f32 %0, %1, %2;" : "=r"(r) : "f"(hi), "f"(lo));
  return r;
}
__device__ __forceinline__ void split2(float v0, float v1, uint32_t& hi, uint32_t& lo) {
  hi = cvt2(v0, v1);
  float r0 = v0 - __uint_as_float(hi << 16);
  float r1 = v1 - __uint_as_float(hi & 0xFFFF0000u);
  lo = cvt2(r0, r1);
}
__device__ __forceinline__ void mma16816(float* d, const uint32_t* a, uint32_t b0, uint32_t b1) {
  asm volatile(
      "mma.sync.aligned.m16n8k16.row.col.f32.bf16.bf16.f32 "
      "{%0,%1,%2,%3}, {%4,%5,%6,%7}, {%8,%9}, {%0,%1,%2,%3};"
      : "+f"(d[0]), "+f"(d[1]), "+f"(d[2]), "+f"(d[3])
      : "r"(a[0]), "r"(a[1]), "r"(a[2]), "r"(a[3]), "r"(b0), "r"(b1));
}

// ---- precompute: one block per 64-basis stripe, transposed W writes via smem ----
__global__ __launch_bounds__(256)
void precompute_kernel(const float* __restrict__ eps,
                       const float* __restrict__ lam,
                       const float* __restrict__ eta,
                       const float* __restrict__ w) {
  __shared__ float Ws[64][67], Wc[64][67];   // [b_local][d], pad 67 (conflict-free transpose)
  const int b0  = blockIdx.x * 64;
  const int tid = threadIdx.x;
  const float et2 = eta[0] * eta[0];

  #pragma unroll
  for (int i = 0; i < 16; i++) {
    int j = tid + i * 256;          // 0..4095
    int b = j >> 6, d = j & 63;
    int idx = (b0 + b) * DD + d;
    float e = eps[idx], la = lam[d];
    float sv = e / (PI_F * la);     // angle = pi * (x . col)
    __nv_bfloat16 h = __float2bfloat16(sv);
    g_Shi[idx] = h;
    g_Slo[idx] = __float2bfloat16(sv - __bfloat162float(h));
    float m;
    if (d < 32) {
      m = eps[(b0 + b) * DD + d + 32] / lam[d + 32];
    } else {
      m = -eps[(b0 + b) * DD + d - 32] / lam[d - 32] - et2 * (e / la);
    }
    Ws[b][d] = -m * w[b0 + b];          // -sin sign folded in
    Wc[b][d] =  m * w[BAS + b0 + b];
  }
  __syncthreads();
  #pragma unroll
  for (int i = 0; i < 16; i++) {
    int j = tid + i * 256;
    int d = j >> 6, b = j & 63;     // consecutive tid -> consecutive b: coalesced stores
    size_t o = (size_t)d * BAS + b0 + b;
    float ws = Ws[b][d], wc = Wc[b][d];
    __nv_bfloat16 h = __float2bfloat16(ws);
    g_Wsh[o] = h;
    g_Wsl[o] = __float2bfloat16(ws - __bfloat162float(h));
    h = __float2bfloat16(wc);
    g_Wch[o] = h;
    g_Wcl[o] = __float2bfloat16(wc - __bfloat162float(h));
  }
}

__global__ __launch_bounds__(THREADS, 2)
void ssgp_mma_kernel(const float* __restrict__ x) {
  extern __shared__ char sm[];
  const int tid  = threadIdx.x;
  const int wid  = tid >> 5;
  const int lane = tid & 31;
  const int gr   = lane >> 2;         // group row 0..7
  const int kl   = (lane & 3) * 2;    // k-pair base 0,2,4,6
  const int rb   = blockIdx.x >> 2;
  const int sp   = blockIdx.x & 3;
  const int r0   = rb * MROWS;

  // ---- prolog: stage X fp32 into scratch (coalesced), extract persistent A-frags ----
  {
    float* Xs = reinterpret_cast<float*>(sm + OFF_XS);   // [128][68]
    #pragma unroll
    for (int i = 0; i < 8; i++) {
      int id  = tid + i * THREADS;     // 0..2047 float4s
      int row = id >> 4;
      int c4  = (id & 15) * 4;
      *reinterpret_cast<float4*>(&Xs[row * 68 + c4]) =
          *reinterpret_cast<const float4*>(&x[(size_t)(r0 + row) * DD + c4]);
    }
  }
  __syncthreads();
  uint32_t Xhi[4][4], Xlo[4][4];
  {
    const float* Xs = reinterpret_cast<const float*>(sm + OFF_XS);
    #pragma unroll
    for (int kt = 0; kt < 4; kt++)
      #pragma unroll
      for (int q = 0; q < 4; q++) {
        int rr = wid * 16 + gr + (q & 1) * 8;
        int kk = kt * 16 + kl + (q >> 1) * 8;
        float2 v = *reinterpret_cast<const float2*>(&Xs[rr * 68 + kk]);
        split2(v.x, v.y, Xhi[kt][q], Xlo[kt][q]);
      }
  }
  __syncthreads();

  float f[8][4] = {};   // persistent output accum: 8 n-tiles x 4 regs

  #pragma unroll 1
  for (int it = 0; it < ITERS; it++) {
    const int b0 = sp * (BAS / SPLITS) + it * NB;

    // ---- stage S tiles (hi/lo): 64 x 64 bf16 each, row pad 72 ----
    #pragma unroll
    for (int i = 0; i < 4; i++) {
      int id   = tid + i * THREADS;    // 0..1023 granules (16B)
      int tile = id >> 9;
      int rem  = id & 511;
      int row  = rem >> 3;
      int c8   = rem & 7;
      const __nv_bfloat16* src = (tile ? g_Slo : g_Shi) + (size_t)(b0 + row) * DD + c8 * 8;
      char* dst = sm + (tile ? OFF_SLO : OFF_SHI) + (row * 72 + c8 * 8) * 2;
      *reinterpret_cast<uint4*>(dst) = *reinterpret_cast<const uint4*>(src);
    }
    // ---- stage W tiles (hi/lo): 64 x 128 bf16 each, row pad 136; k 0..63 sin, 64..127 cos ----
    #pragma unroll
    for (int i = 0; i < 8; i++) {
      int id   = tid + i * THREADS;    // 0..2047 granules
      int tile = id >> 10;
      int rem  = id & 1023;
      int row  = rem >> 4;
      int part = (rem >> 3) & 1;
      int c8   = rem & 7;
      const __nv_bfloat16* src =
          (tile ? (part ? g_Wcl : g_Wsl) : (part ? g_Wch : g_Wsh)) + (size_t)row * BAS + b0 + c8 * 8;
      char* dst = sm + (tile ? OFF_WLO : OFF_WHI) + (row * 136 + part * 64 + c8 * 8) * 2;
      *reinterpret_cast<uint4*>(dst) = *reinterpret_cast<const uint4*>(src);
    }
    __syncthreads();

    // ---- 4 basis-pairs: GEMM1 (reg angles) -> sincos/split -> GEMM2 accumulate ----
    #pragma unroll
    for (int p = 0; p < 4; p++) {
      // GEMM1 with split accumulators: Da = hi*hi (4-chain), Db = cross terms (8-chain)
      float Da[2][4] = {}, Db[2][4] = {};
      #pragma unroll
      for (int kt = 0; kt < 4; kt++) {
        #pragma unroll
        for (int j = 0; j < 2; j++) {
          int e = ((2 * p + j) * 8 + gr) * 72 + kt * 16 + kl;
          const char* sh = sm + OFF_SHI + e * 2;
          const char* sl = sm + OFF_SLO + e * 2;
          uint32_t bh0 = *reinterpret_cast<const uint32_t*>(sh);
          uint32_t bh1 = *reinterpret_cast<const uint32_t*>(sh + 16);
          uint32_t bl0 = *reinterpret_cast<const uint32_t*>(sl);
          uint32_t bl1 = *reinterpret_cast<const uint32_t*>(sl + 16);
          mma16816(Da[j], Xhi[kt], bh0, bh1);
          mma16816(Db[j], Xhi[kt], bl0, bl1);
          mma16816(Db[j], Xlo[kt], bh0, bh1);
        }
      }

      // sincos + bf16 split, packed directly as GEMM2 A-frags (D-frag == A-frag layout)
      uint32_t Ash[4], Asl[4], Ach[4], Acl[4];
      #pragma unroll
      for (int j = 0; j < 2; j++)
        #pragma unroll
        for (int h = 0; h < 2; h++) {
          float v0 = Da[j][2 * h]     + Db[j][2 * h];
          float v1 = Da[j][2 * h + 1] + Db[j][2 * h + 1];
          float a0 = fmaf(-2.0f, rintf(v0 * 0.5f), v0) * PI_F;
          float a1 = fmaf(-2.0f, rintf(v1 * 0.5f), v1) * PI_F;
          float s0, c0, s1, c1;
          __sincosf(a0, &s0, &c0);
          __sincosf(a1, &s1, &c1);
          int idx = 2 * j + h;
          split2(s0, s1, Ash[idx], Asl[idx]);
          split2(c0, c1, Ach[idx], Acl[idx]);
        }

      // GEMM2: f[nt] += P(16x16 sin | 16x16 cos) . W^T  (3 split passes each)
      #pragma unroll
      for (int nt = 0; nt < 8; nt++) {
        int ebase = (nt * 8 + gr) * 136 + kl;
        {
          int e = ebase + 16 * p;                 // sin k-tile
          const char* wh = sm + OFF_WHI + e * 2;
          const char* wl = sm + OFF_WLO + e * 2;
          uint32_t h0 = *reinterpret_cast<const uint32_t*>(wh);
          uint32_t h1 = *reinterpret_cast<const uint32_t*>(wh + 16);
          uint32_t l0 = *reinterpret_cast<const uint32_t*>(wl);
          uint32_t l1 = *reinterpret_cast<const uint32_t*>(wl + 16);
          mma16816(f[nt], Ash, h0, h1);
          mma16816(f[nt], Ash, l0, l1);
          mma16816(f[nt], Asl, h0, h1);
        }
        {
          int e = ebase + 64 + 16 * p;            // cos k-tile
          const char* wh = sm + OFF_WHI + e * 2;
          const char* wl = sm + OFF_WLO + e * 2;
          uint32_t h0 = *reinterpret_cast<const uint32_t*>(wh);
          uint32_t h1 = *reinterpret_cast<const uint32_t*>(wh + 16);
          uint32_t l0 = *reinterpret_cast<const uint32_t*>(wl);
          uint32_t l1 = *reinterpret_cast<const uint32_t*>(wl + 16);
          mma16816(f[nt], Ach, h0, h1);
          mma16816(f[nt], Ach, l0, l1);
          mma16816(f[nt], Acl, h0, h1);
        }
      }
    }
    __syncthreads();   // before restaging next tile
  }

  // ---- epilogue: write partials ----
  {
    float* po = g_part + (size_t)sp * NROWS * DD;
    int row = r0 + wid * 16 + gr;
    #pragma unroll
    for (int nt = 0; nt < 8; nt++) {
      int col = nt * 8 + kl;
      *reinterpret_cast<float2*>(&po[(size_t)row * DD + col]) =
          make_float2(f[nt][0], f[nt][1]);
      *reinterpret_cast<float2*>(&po[(size_t)(row + 8) * DD + col]) =
          make_float2(f[nt][2], f[nt][3]);
    }
  }
}

__global__ void reduce_kernel(float* __restrict__ out) {
  int i = blockIdx.x * blockDim.x + threadIdx.x;
  constexpr int N4 = NROWS * DD / 4;
  if (i >= N4) return;
  const float4* p = reinterpret_cast<const float4*>(g_part);
  float4 a = p[i];
  #pragma unroll
  for (int s = 1; s < SPLITS; s++) {
    float4 b = p[(size_t)s * N4 + i];
    a.x += b.x; a.y += b.y; a.z += b.z; a.w += b.w;
  }
  reinterpret_cast<float4*>(out)[i] = a;
}

extern "C" void kernel_launch(void* const* d_in, const int* in_sizes, int n_in,
                              void* d_out, int out_size) {
  // inputs (metadata order): t, x, epsilon, lam, eta, w
  const float* x_in = (const float*)d_in[1];
  const float* eps  = (const float*)d_in[2];
  const float* lam  = (const float*)d_in[3];
  const float* eta  = (const float*)d_in[4];
  const float* w    = (const float*)d_in[5];
  float* out = (float*)d_out;

  cudaFuncSetAttribute(ssgp_mma_kernel,
                       cudaFuncAttributeMaxDynamicSharedMemorySize, SMEM_BYTES);

  precompute_kernel<<<BAS / 64, 256>>>(eps, lam, eta, w);
  ssgp_mma_kernel<<<(NROWS / MROWS) * SPLITS, THREADS, SMEM_BYTES>>>(x_in);
  reduce_kernel<<<(NROWS * DD / 4 + 255) / 256, 256>>>(out);
}

// round 7
// speedup vs baseline: 6.0201x; 1.2603x over previous
#include <cuda_runtime.h>
#include <cuda_fp16.h>
#include <cstdint>

#define PI_F 3.14159265358979323846f
#define WSCALE 1024.0f

constexpr int NROWS = 8192, DD = 64, BAS = 2048;
constexpr int MROWS   = 128;                 // rows per CTA (8 warps x 16)
constexpr int NB      = 64;                  // basis per iteration
constexpr int SPLITS  = 4;
constexpr int ITERS   = BAS / SPLITS / NB;   // 8
constexpr int THREADS = 256;

// smem byte offsets
constexpr int OFF_SHI = 0;        // 64 x 72 fp16 = 9216
constexpr int OFF_SLO = 9216;     // 64 x 72 fp16
constexpr int OFF_WHI = 18432;    // 64 x 136 fp16 = 17408  (k: 0..63 sin, 64..127 cos)
constexpr int OFF_WLO = 35840;    // 64 x 136 fp16
constexpr int OFF_XS  = OFF_WHI;  // overlay scratch: 128 x 68 f32 = 34816 (dead after prolog)
constexpr int SMEM_BYTES = 53248;

__device__ __half g_Shi[BAS * DD], g_Slo[BAS * DD];   // [b][d]
__device__ __half g_Wsh[DD * BAS], g_Wsl[DD * BAS];   // [c][b]  sin coeff (-mat*w_s*1024)
__device__ __half g_Wch[DD * BAS], g_Wcl[DD * BAS];   // [c][b]  cos coeff ( mat*w_c*1024)
__device__ float g_part[SPLITS * NROWS * DD];

__device__ __forceinline__ uint32_t h2(float v0, float v1) {
  __half2 h = __floats2half2_rn(v0, v1);
  return *reinterpret_cast<uint32_t*>(&h);
}
__device__ __forceinline__ void split2h(float v0, float v1, uint32_t& hi, uint32_t& lo) {
  hi = h2(v0, v1);
  float2 hf = __half22float2(*reinterpret_cast<__half2*>(&hi));
  lo = h2(v0 - hf.x, v1 - hf.y);
}
__device__ __forceinline__ void mma16816(float* d, const uint32_t* a, uint32_t b0, uint32_t b1) {
  asm volatile(
      "mma.sync.aligned.m16n8k16.row.col.f32.f16.f16.f32 "
      "{%0,%1,%2,%3}, {%4,%5,%6,%7}, {%8,%9}, {%0,%1,%2,%3};"
      : "+f"(d[0]), "+f"(d[1]), "+f"(d[2]), "+f"(d[3])
      : "r"(a[0]), "r"(a[1]), "r"(a[2]), "r"(a[3]), "r"(b0), "r"(b1));
}

// ---- precompute: one block per 16-basis stripe (grid 128), transposed W via smem ----
__global__ __launch_bounds__(256)
void precompute_kernel(const float* __restrict__ eps,
                       const float* __restrict__ lam,
                       const float* __restrict__ eta,
                       const float* __restrict__ w) {
  __shared__ float Ws[16][67], Wc[16][67];
  const int b0  = blockIdx.x * 16;
  const int tid = threadIdx.x;
  const float et2 = eta[0] * eta[0];

  #pragma unroll
  for (int i = 0; i < 4; i++) {
    int j = tid + i * 256;          // 0..1023
    int b = j >> 6, d = j & 63;
    int idx = (b0 + b) * DD + d;
    float e = eps[idx], la = lam[d];
    float sv = e / (PI_F * la);     // angle = pi * (x . col)
    __half h = __float2half_rn(sv);
    g_Shi[idx] = h;
    g_Slo[idx] = __float2half_rn(sv - __half2float(h));
    float m;
    if (d < 32) {
      m = eps[(b0 + b) * DD + d + 32] / lam[d + 32];
    } else {
      m = -eps[(b0 + b) * DD + d - 32] / lam[d - 32] - et2 * (e / la);
    }
    Ws[b][d] = -m * w[b0 + b] * WSCALE;        // -sin sign folded in
    Wc[b][d] =  m * w[BAS + b0 + b] * WSCALE;
  }
  __syncthreads();
  #pragma unroll
  for (int i = 0; i < 4; i++) {
    int j = tid + i * 256;          // 0..1023
    int d = j >> 4, b = j & 15;
    size_t o = (size_t)d * BAS + b0 + b;
    float ws = Ws[b][d], wc = Wc[b][d];
    __half h = __float2half_rn(ws);
    g_Wsh[o] = h;
    g_Wsl[o] = __float2half_rn(ws - __half2float(h));
    h = __float2half_rn(wc);
    g_Wch[o] = h;
    g_Wcl[o] = __float2half_rn(wc - __half2float(h));
  }
}

__global__ __launch_bounds__(THREADS, 2)
void ssgp_mma_kernel(const float* __restrict__ x) {
  extern __shared__ char sm[];
  const int tid  = threadIdx.x;
  const int wid  = tid >> 5;
  const int lane = tid & 31;
  const int gr   = lane >> 2;         // group row 0..7
  const int kl   = (lane & 3) * 2;    // k-pair base 0,2,4,6
  const int rb   = blockIdx.x >> 2;
  const int sp   = blockIdx.x & 3;
  const int r0   = rb * MROWS;

  // ---- prolog: stage X fp32 into scratch (coalesced), extract persistent A-frags ----
  {
    float* Xs = reinterpret_cast<float*>(sm + OFF_XS);   // [128][68]
    #pragma unroll
    for (int i = 0; i < 8; i++) {
      int id  = tid + i * THREADS;     // 0..2047 float4s
      int row = id >> 4;
      int c4  = (id & 15) * 4;
      *reinterpret_cast<float4*>(&Xs[row * 68 + c4]) =
          *reinterpret_cast<const float4*>(&x[(size_t)(r0 + row) * DD + c4]);
    }
  }
  __syncthreads();
  uint32_t Xhi[4][4], Xlo[4][4];
  {
    const float* Xs = reinterpret_cast<const float*>(sm + OFF_XS);
    #pragma unroll
    for (int kt = 0; kt < 4; kt++)
      #pragma unroll
      for (int q = 0; q < 4; q++) {
        int rr = wid * 16 + gr + (q & 1) * 8;
        int kk = kt * 16 + kl + (q >> 1) * 8;
        float2 v = *reinterpret_cast<const float2*>(&Xs[rr * 68 + kk]);
        split2h(v.x, v.y, Xhi[kt][q], Xlo[kt][q]);
      }
  }
  __syncthreads();

  float f[8][4] = {};   // persistent output accum: 8 n-tiles x 4 regs

  #pragma unroll 1
  for (int it = 0; it < ITERS; it++) {
    const int b0 = sp * (BAS / SPLITS) + it * NB;

    // ---- stage S tiles (hi/lo): 64 x 64 fp16 each, row pad 72 ----
    #pragma unroll
    for (int i = 0; i < 4; i++) {
      int id   = tid + i * THREADS;    // 0..1023 granules (16B)
      int tile = id >> 9;
      int rem  = id & 511;
      int row  = rem >> 3;
      int c8   = rem & 7;
      const __half* src = (tile ? g_Slo : g_Shi) + (size_t)(b0 + row) * DD + c8 * 8;
      char* dst = sm + (tile ? OFF_SLO : OFF_SHI) + (row * 72 + c8 * 8) * 2;
      *reinterpret_cast<uint4*>(dst) = *reinterpret_cast<const uint4*>(src);
    }
    // ---- stage W tiles (hi/lo): 64 x 128 fp16 each, row pad 136; k 0..63 sin, 64..127 cos ----
    #pragma unroll
    for (int i = 0; i < 8; i++) {
      int id   = tid + i * THREADS;    // 0..2047 granules
      int tile = id >> 10;
      int rem  = id & 1023;
      int row  = rem >> 4;
      int part = (rem >> 3) & 1;
      int c8   = rem & 7;
      const __half* src =
          (tile ? (part ? g_Wcl : g_Wsl) : (part ? g_Wch : g_Wsh)) + (size_t)row * BAS + b0 + c8 * 8;
      char* dst = sm + (tile ? OFF_WLO : OFF_WHI) + (row * 136 + part * 64 + c8 * 8) * 2;
      *reinterpret_cast<uint4*>(dst) = *reinterpret_cast<const uint4*>(src);
    }
    __syncthreads();

    // ---- 4 basis-pairs: GEMM1 (reg angles) -> sincos -> GEMM2 accumulate ----
    #pragma unroll
    for (int p = 0; p < 4; p++) {
      // GEMM1 split accumulators: Da = hi*hi (4-chain), Db = cross terms (8-chain)
      float Da[2][4] = {}, Db[2][4] = {};
      #pragma unroll
      for (int kt = 0; kt < 4; kt++) {
        #pragma unroll
        for (int j = 0; j < 2; j++) {
          int e = ((2 * p + j) * 8 + gr) * 72 + kt * 16 + kl;
          const char* sh = sm + OFF_SHI + e * 2;
          const char* sl = sm + OFF_SLO + e * 2;
          uint32_t bh0 = *reinterpret_cast<const uint32_t*>(sh);
          uint32_t bh1 = *reinterpret_cast<const uint32_t*>(sh + 16);
          uint32_t bl0 = *reinterpret_cast<const uint32_t*>(sl);
          uint32_t bl1 = *reinterpret_cast<const uint32_t*>(sl + 16);
          mma16816(Da[j], Xhi[kt], bh0, bh1);
          mma16816(Db[j], Xhi[kt], bl0, bl1);
          mma16816(Db[j], Xlo[kt], bh0, bh1);
        }
      }

      // sincos; pack hi-only fp16 A-frags for GEMM2 (D-frag == A-frag layout)
      uint32_t Ash[4], Ach[4];
      #pragma unroll
      for (int j = 0; j < 2; j++)
        #pragma unroll
        for (int h = 0; h < 2; h++) {
          float v0 = Da[j][2 * h]     + Db[j][2 * h];
          float v1 = Da[j][2 * h + 1] + Db[j][2 * h + 1];
          float a0 = fmaf(-2.0f, rintf(v0 * 0.5f), v0) * PI_F;
          float a1 = fmaf(-2.0f, rintf(v1 * 0.5f), v1) * PI_F;
          float s0, c0, s1, c1;
          __sincosf(a0, &s0, &c0);
          __sincosf(a1, &s1, &c1);
          int idx = 2 * j + h;
          Ash[idx] = h2(s0, s1);
          Ach[idx] = h2(c0, c1);
        }

      // GEMM2: f[nt] += Ph . (Wh + Wl)^T  (2 passes per trig part)
      #pragma unroll
      for (int nt = 0; nt < 8; nt++) {
        int ebase = (nt * 8 + gr) * 136 + kl;
        {
          int e = ebase + 16 * p;                 // sin k-tile
          const char* wh = sm + OFF_WHI + e * 2;
          const char* wl = sm + OFF_WLO + e * 2;
          uint32_t h0 = *reinterpret_cast<const uint32_t*>(wh);
          uint32_t h1 = *reinterpret_cast<const uint32_t*>(wh + 16);
          uint32_t l0 = *reinterpret_cast<const uint32_t*>(wl);
          uint32_t l1 = *reinterpret_cast<const uint32_t*>(wl + 16);
          mma16816(f[nt], Ash, h0, h1);
          mma16816(f[nt], Ash, l0, l1);
        }
        {
          int e = ebase + 64 + 16 * p;            // cos k-tile
          const char* wh = sm + OFF_WHI + e * 2;
          const char* wl = sm + OFF_WLO + e * 2;
          uint32_t h0 = *reinterpret_cast<const uint32_t*>(wh);
          uint32_t h1 = *reinterpret_cast<const uint32_t*>(wh + 16);
          uint32_t l0 = *reinterpret_cast<const uint32_t*>(wl);
          uint32_t l1 = *reinterpret_cast<const uint32_t*>(wl + 16);
          mma16816(f[nt], Ach, h0, h1);
          mma16816(f[nt], Ach, l0, l1);
        }
      }
    }
    __syncthreads();   // before restaging next tile
  }

  // ---- epilogue: write partials ----
  {
    float* po = g_part + (size_t)sp * NROWS * DD;
    int row = r0 + wid * 16 + gr;
    #pragma unroll
    for (int nt = 0; nt < 8; nt++) {
      int col = nt * 8 + kl;
      *reinterpret_cast<float2*>(&po[(size_t)row * DD + col]) =
          make_float2(f[nt][0], f[nt][1]);
      *reinterpret_cast<float2*>(&po[(size_t)(row + 8) * DD + col]) =
          make_float2(f[nt][2], f[nt][3]);
    }
  }
}

__global__ void reduce_kernel(float* __restrict__ out) {
  int i = blockIdx.x * blockDim.x + threadIdx.x;
  constexpr int N4 = NROWS * DD / 4;
  if (i >= N4) return;
  const float4* p = reinterpret_cast<const float4*>(g_part);
  float4 a = p[i];
  #pragma unroll
  for (int s = 1; s < SPLITS; s++) {
    float4 b = p[(size_t)s * N4 + i];
    a.x += b.x; a.y += b.y; a.z += b.z; a.w += b.w;
  }
  const float inv = 1.0f / WSCALE;
  a.x *= inv; a.y *= inv; a.z *= inv; a.w *= inv;
  reinterpret_cast<float4*>(out)[i] = a;
}

extern "C" void kernel_launch(void* const* d_in, const int* in_sizes, int n_in,
                              void* d_out, int out_size) {
  // inputs (metadata order): t, x, epsilon, lam, eta, w
  const float* x_in = (const float*)d_in[1];
  const float* eps  = (const float*)d_in[2];
  const float* lam  = (const float*)d_in[3];
  const float* eta  = (const float*)d_in[4];
  const float* w    = (const float*)d_in[5];
  float* out = (float*)d_out;

  cudaFuncSetAttribute(ssgp_mma_kernel,
                       cudaFuncAttributeMaxDynamicSharedMemorySize, SMEM_BYTES);

  precompute_kernel<<<BAS / 16, 256>>>(eps, lam, eta, w);
  ssgp_mma_kernel<<<(NROWS / MROWS) * SPLITS, THREADS, SMEM_BYTES>>>(x_in);
  reduce_kernel<<<(NROWS * DD / 4 + 255) / 256, 256>>>(out);
}

// round 8
// speedup vs baseline: 7.7031x; 1.2796x over previous
#include <cuda_runtime.h>
#include <cuda_fp16.h>
#include <cstdint>

#define PI_F 3.14159265358979323846f
#define WSCALE 1024.0f

constexpr int NROWS = 8192, DD = 64, BAS = 2048;
constexpr int MROWS   = 128;                 // rows per CTA (8 warps x 16)
constexpr int NB      = 64;                  // basis per iteration
constexpr int SPLITS  = 4;
constexpr int ITERS   = BAS / SPLITS / NB;   // 8
constexpr int THREADS = 256;

// smem byte offsets
constexpr int OFF_SHI = 0;        // 64 x 72 fp16 = 9216
constexpr int OFF_SLO = 9216;     // 64 x 72 fp16
constexpr int OFF_WHI = 18432;    // 64 x 136 fp16 = 17408  (k: 0..63 sin, 64..127 cos)
constexpr int OFF_XS  = 0;        // overlay scratch: 128 x 68 f32 = 34816 (dead after prolog)
constexpr int SMEM_BYTES = 36864;

__device__ __half g_Shi[BAS * DD], g_Slo[BAS * DD];   // [b][d]
__device__ __half g_Wsh[DD * BAS];                    // [c][b]  sin coeff (-mat*w_s*1024)
__device__ __half g_Wch[DD * BAS];                    // [c][b]  cos coeff ( mat*w_c*1024)
__device__ float g_part[SPLITS * NROWS * DD];

__device__ __forceinline__ uint32_t h2(float v0, float v1) {
  __half2 h = __floats2half2_rn(v0, v1);
  return *reinterpret_cast<uint32_t*>(&h);
}
__device__ __forceinline__ void split2h(float v0, float v1, uint32_t& hi, uint32_t& lo) {
  hi = h2(v0, v1);
  float2 hf = __half22float2(*reinterpret_cast<__half2*>(&hi));
  lo = h2(v0 - hf.x, v1 - hf.y);
}
__device__ __forceinline__ void mma16816(float* d, const uint32_t* a, uint32_t b0, uint32_t b1) {
  asm volatile(
      "mma.sync.aligned.m16n8k16.row.col.f32.f16.f16.f32 "
      "{%0,%1,%2,%3}, {%4,%5,%6,%7}, {%8,%9}, {%0,%1,%2,%3};"
      : "+f"(d[0]), "+f"(d[1]), "+f"(d[2]), "+f"(d[3])
      : "r"(a[0]), "r"(a[1]), "r"(a[2]), "r"(a[3]), "r"(b0), "r"(b1));
}

// ---- precompute: one block per 8-basis stripe (grid 256), transposed W via smem ----
__global__ __launch_bounds__(256)
void precompute_kernel(const float* __restrict__ eps,
                       const float* __restrict__ lam,
                       const float* __restrict__ eta,
                       const float* __restrict__ w) {
  __shared__ float Ws[8][67], Wc[8][67];
  const int b0  = blockIdx.x * 8;
  const int tid = threadIdx.x;
  const float et2 = eta[0] * eta[0];

  #pragma unroll
  for (int i = 0; i < 2; i++) {
    int j = tid + i * 256;          // 0..511
    int b = j >> 6, d = j & 63;
    int idx = (b0 + b) * DD + d;
    float e = eps[idx], la = lam[d];
    float sv = e / (PI_F * la);     // angle = pi * (x . col)
    __half h = __float2half_rn(sv);
    g_Shi[idx] = h;
    g_Slo[idx] = __float2half_rn(sv - __half2float(h));
    float m;
    if (d < 32) {
      m = eps[(b0 + b) * DD + d + 32] / lam[d + 32];
    } else {
      m = -eps[(b0 + b) * DD + d - 32] / lam[d - 32] - et2 * (e / la);
    }
    Ws[b][d] = -m * w[b0 + b] * WSCALE;        // -sin sign folded in
    Wc[b][d] =  m * w[BAS + b0 + b] * WSCALE;
  }
  __syncthreads();
  #pragma unroll
  for (int i = 0; i < 2; i++) {
    int j = tid + i * 256;          // 0..511
    int d = j >> 3, b = j & 7;
    size_t o = (size_t)d * BAS + b0 + b;
    g_Wsh[o] = __float2half_rn(Ws[b][d]);
    g_Wch[o] = __float2half_rn(Wc[b][d]);
  }
}

__global__ __launch_bounds__(THREADS, 2)
void ssgp_mma_kernel(const float* __restrict__ x) {
  extern __shared__ char sm[];
  const int tid  = threadIdx.x;
  const int wid  = tid >> 5;
  const int lane = tid & 31;
  const int gr   = lane >> 2;         // group row 0..7
  const int kl   = (lane & 3) * 2;    // k-pair base 0,2,4,6
  const int rb   = blockIdx.x >> 2;
  const int sp   = blockIdx.x & 3;
  const int r0   = rb * MROWS;

  // ---- prolog: stage X fp32 into scratch (coalesced), extract persistent A-frags ----
  {
    float* Xs = reinterpret_cast<float*>(sm + OFF_XS);   // [128][68]
    #pragma unroll
    for (int i = 0; i < 8; i++) {
      int id  = tid + i * THREADS;     // 0..2047 float4s
      int row = id >> 4;
      int c4  = (id & 15) * 4;
      *reinterpret_cast<float4*>(&Xs[row * 68 + c4]) =
          *reinterpret_cast<const float4*>(&x[(size_t)(r0 + row) * DD + c4]);
    }
  }
  __syncthreads();
  uint32_t Xhi[4][4], Xlo[4][4];
  {
    const float* Xs = reinterpret_cast<const float*>(sm + OFF_XS);
    #pragma unroll
    for (int kt = 0; kt < 4; kt++)
      #pragma unroll
      for (int q = 0; q < 4; q++) {
        int rr = wid * 16 + gr + (q & 1) * 8;
        int kk = kt * 16 + kl + (q >> 1) * 8;
        float2 v = *reinterpret_cast<const float2*>(&Xs[rr * 68 + kk]);
        split2h(v.x, v.y, Xhi[kt][q], Xlo[kt][q]);
      }
  }
  __syncthreads();

  float f[8][4] = {};   // persistent output accum: 8 n-tiles x 4 regs

  #pragma unroll 1
  for (int it = 0; it < ITERS; it++) {
    const int b0 = sp * (BAS / SPLITS) + it * NB;

    // ---- stage S tiles (hi/lo): 64 x 64 fp16 each, row pad 72 ----
    #pragma unroll
    for (int i = 0; i < 4; i++) {
      int id   = tid + i * THREADS;    // 0..1023 granules (16B)
      int tile = id >> 9;
      int rem  = id & 511;
      int row  = rem >> 3;
      int c8   = rem & 7;
      const __half* src = (tile ? g_Slo : g_Shi) + (size_t)(b0 + row) * DD + c8 * 8;
      char* dst = sm + (tile ? OFF_SLO : OFF_SHI) + (row * 72 + c8 * 8) * 2;
      *reinterpret_cast<uint4*>(dst) = *reinterpret_cast<const uint4*>(src);
    }
    // ---- stage W tile (hi only): 64 x 128 fp16, row pad 136; k 0..63 sin, 64..127 cos ----
    #pragma unroll
    for (int i = 0; i < 4; i++) {
      int id   = tid + i * THREADS;    // 0..1023 granules
      int row  = id >> 4;
      int part = (id >> 3) & 1;
      int c8   = id & 7;
      const __half* src = (part ? g_Wch : g_Wsh) + (size_t)row * BAS + b0 + c8 * 8;
      char* dst = sm + OFF_WHI + (row * 136 + part * 64 + c8 * 8) * 2;
      *reinterpret_cast<uint4*>(dst) = *reinterpret_cast<const uint4*>(src);
    }
    __syncthreads();

    // ---- 4 basis-pairs: GEMM1 (reg angles) -> sincos -> GEMM2 accumulate ----
    #pragma unroll
    for (int p = 0; p < 4; p++) {
      // GEMM1 split accumulators: Da = hi*hi (4-chain), Db = cross terms (8-chain)
      float Da[2][4] = {}, Db[2][4] = {};
      #pragma unroll
      for (int kt = 0; kt < 4; kt++) {
        #pragma unroll
        for (int j = 0; j < 2; j++) {
          int e = ((2 * p + j) * 8 + gr) * 72 + kt * 16 + kl;
          const char* sh = sm + OFF_SHI + e * 2;
          const char* sl = sm + OFF_SLO + e * 2;
          uint32_t bh0 = *reinterpret_cast<const uint32_t*>(sh);
          uint32_t bh1 = *reinterpret_cast<const uint32_t*>(sh + 16);
          uint32_t bl0 = *reinterpret_cast<const uint32_t*>(sl);
          uint32_t bl1 = *reinterpret_cast<const uint32_t*>(sl + 16);
          mma16816(Da[j], Xhi[kt], bh0, bh1);
          mma16816(Db[j], Xhi[kt], bl0, bl1);
          mma16816(Db[j], Xlo[kt], bh0, bh1);
        }
      }

      // sincos; pack hi-only fp16 A-frags for GEMM2 (D-frag == A-frag layout)
      uint32_t Ash[4], Ach[4];
      #pragma unroll
      for (int j = 0; j < 2; j++)
        #pragma unroll
        for (int h = 0; h < 2; h++) {
          float v0 = Da[j][2 * h]     + Db[j][2 * h];
          float v1 = Da[j][2 * h + 1] + Db[j][2 * h + 1];
          float a0 = fmaf(-2.0f, rintf(v0 * 0.5f), v0) * PI_F;
          float a1 = fmaf(-2.0f, rintf(v1 * 0.5f), v1) * PI_F;
          float s0, c0, s1, c1;
          __sincosf(a0, &s0, &c0);
          __sincosf(a1, &s1, &c1);
          int idx = 2 * j + h;
          Ash[idx] = h2(s0, s1);
          Ach[idx] = h2(c0, c1);
        }

      // GEMM2: f[nt] += Ph_sin . Wsin^T + Ph_cos . Wcos^T  (hi-only W)
      #pragma unroll
      for (int nt = 0; nt < 8; nt++) {
        int ebase = (nt * 8 + gr) * 136 + kl;
        const char* ws = sm + OFF_WHI + (ebase + 16 * p) * 2;        // sin k-tile
        const char* wc = sm + OFF_WHI + (ebase + 64 + 16 * p) * 2;   // cos k-tile
        uint32_t s0 = *reinterpret_cast<const uint32_t*>(ws);
        uint32_t s1 = *reinterpret_cast<const uint32_t*>(ws + 16);
        uint32_t c0 = *reinterpret_cast<const uint32_t*>(wc);
        uint32_t c1 = *reinterpret_cast<const uint32_t*>(wc + 16);
        mma16816(f[nt], Ash, s0, s1);
        mma16816(f[nt], Ach, c0, c1);
      }
    }
    __syncthreads();   // before restaging next tile
  }

  // ---- epilogue: write partials ----
  {
    float* po = g_part + (size_t)sp * NROWS * DD;
    int row = r0 + wid * 16 + gr;
    #pragma unroll
    for (int nt = 0; nt < 8; nt++) {
      int col = nt * 8 + kl;
      *reinterpret_cast<float2*>(&po[(size_t)row * DD + col]) =
          make_float2(f[nt][0], f[nt][1]);
      *reinterpret_cast<float2*>(&po[(size_t)(row + 8) * DD + col]) =
          make_float2(f[nt][2], f[nt][3]);
    }
  }
}

__global__ void reduce_kernel(float* __restrict__ out) {
  int i = blockIdx.x * blockDim.x + threadIdx.x;
  constexpr int N4 = NROWS * DD / 4;
  if (i >= N4) return;
  const float4* p = reinterpret_cast<const float4*>(g_part);
  float4 a = p[i];
  #pragma unroll
  for (int s = 1; s < SPLITS; s++) {
    float4 b = p[(size_t)s * N4 + i];
    a.x += b.x; a.y += b.y; a.z += b.z; a.w += b.w;
  }
  const float inv = 1.0f / WSCALE;
  a.x *= inv; a.y *= inv; a.z *= inv; a.w *= inv;
  reinterpret_cast<float4*>(out)[i] = a;
}

extern "C" void kernel_launch(void* const* d_in, const int* in_sizes, int n_in,
                              void* d_out, int out_size) {
  // inputs (metadata order): t, x, epsilon, lam, eta, w
  const float* x_in = (const float*)d_in[1];
  const float* eps  = (const float*)d_in[2];
  const float* lam  = (const float*)d_in[3];
  const float* eta  = (const float*)d_in[4];
  const float* w    = (const float*)d_in[5];
  float* out = (float*)d_out;

  cudaFuncSetAttribute(ssgp_mma_kernel,
                       cudaFuncAttributeMaxDynamicSharedMemorySize, SMEM_BYTES);

  precompute_kernel<<<BAS / 8, 256>>>(eps, lam, eta, w);
  ssgp_mma_kernel<<<(NROWS / MROWS) * SPLITS, THREADS, SMEM_BYTES>>>(x_in);
  reduce_kernel<<<(NROWS * DD / 4 + 255) / 256, 256>>>(out);
}